// round 11
// baseline (speedup 1.0000x reference)
#include <cuda_runtime.h>
#include <cuda_fp16.h>

#define NN 50000
#define NE 600000
#define HID 128
#define CAP 128          // bucket capacity per segment (max degree ~30 for Poisson(12))

#define ASTRIDE 136

typedef unsigned long long u64;
typedef unsigned int u32;
typedef unsigned short u16;

// ---- scratch ----
__device__ int    g_cnt[2 * NN];          // [0,NN): node degree; [NN,2NN): hedge degree
__device__ u16    g_bkt_n[NN * CAP];      // edges incident to node n
__device__ u16    g_bkt_e[NN * CAP];      // nodes in hyperedge e
__device__ __half g_xh[NN * HID];
__device__ __half g_w1h[HID * HID];
__device__ __half g_w2h[HID * HID];
__device__ __half g_xw[NN * HID];
__device__ __half g_m[NN * HID];
__device__ __half g_h[NN * HID];
__device__ int    g_is_i32;

// ---- streams + events ----
struct SideStream {
    cudaStream_t s1;
    cudaEvent_t evStart, evGemm, evFill;
    SideStream() {
        cudaStreamCreateWithFlags(&s1, cudaStreamNonBlocking);
        cudaEventCreateWithFlags(&evStart, cudaEventDisableTiming);
        cudaEventCreateWithFlags(&evGemm, cudaEventDisableTiming);
        cudaEventCreateWithFlags(&evFill, cudaEventDisableTiming);
    }
};
static SideStream g_ss;

// ---- PTX helpers ----
__device__ __forceinline__ u32 sptr(const void* p) {
    return (u32)__cvta_generic_to_shared(p);
}
__device__ __forceinline__ void ldsm4(u32& r0, u32& r1, u32& r2, u32& r3, u32 a) {
    asm volatile("ldmatrix.sync.aligned.m8n8.x4.shared.b16 {%0,%1,%2,%3},[%4];"
                 : "=r"(r0), "=r"(r1), "=r"(r2), "=r"(r3) : "r"(a));
}
__device__ __forceinline__ void ldsm4t(u32& r0, u32& r1, u32& r2, u32& r3, u32 a) {
    asm volatile("ldmatrix.sync.aligned.m8n8.x4.trans.shared.b16 {%0,%1,%2,%3},[%4];"
                 : "=r"(r0), "=r"(r1), "=r"(r2), "=r"(r3) : "r"(a));
}
__device__ __forceinline__ void mma16816(float* d, const u32* a, const u32* b) {
    asm volatile("mma.sync.aligned.m16n8k16.row.col.f32.f16.f16.f32 "
                 "{%0,%1,%2,%3},{%4,%5,%6,%7},{%8,%9},{%0,%1,%2,%3};"
                 : "+f"(d[0]), "+f"(d[1]), "+f"(d[2]), "+f"(d[3])
                 : "r"(a[0]), "r"(a[1]), "r"(a[2]), "r"(a[3]), "r"(b[0]), "r"(b[1]));
}

// ---- zero counts + dtype detect (block 0) ----
__global__ void k_zero_detect(const long long* __restrict__ hei64) {
    int i = blockIdx.x * blockDim.x + threadIdx.x;
    if (i < 2 * NN) g_cnt[i] = 0;
    if (blockIdx.x == 0) {
        int tid = threadIdx.x;
        int bad = 0;
#pragma unroll
        for (int t = 0; t < 16; t++) {
            long long v = hei64[tid * 16 + t];
            if (v < 0 || v >= NN) bad = 1;
        }
        __shared__ int sbad[8];
        unsigned wb = __ballot_sync(0xffffffffu, bad);
        if ((tid & 31) == 0) sbad[tid >> 5] = (wb != 0);
        __syncthreads();
        if (tid == 0) {
            int any = 0;
            for (int w = 0; w < 8; w++) any |= sbad[w];
            g_is_i32 = any;
        }
    }
}

__device__ __forceinline__ int clampi(int v) {
    return (v < 0 || v >= NN) ? 0 : v;
}

// ---- single-pass bucket CSR fill (both sides), 2 entries / thread ----
__global__ void k_fill(const void* __restrict__ hei) {
    int t = blockIdx.x * blockDim.x + threadIdx.x;
    int i0 = t * 2;
    if (i0 >= NE) return;
    bool i32 = (g_is_i32 != 0);
#pragma unroll
    for (int k = 0; k < 2; k++) {
        int i = i0 + k;
        int n, e;
        if (i32) {
            n = ((const int*)hei)[i];
            e = ((const int*)hei)[NE + i];
        } else {
            n = (int)((const long long*)hei)[i];
            e = (int)((const long long*)hei)[NE + i];
        }
        n = clampi(n);
        e = clampi(e);
        int pn = atomicAdd(&g_cnt[n], 1);
        if (pn < CAP) g_bkt_n[n * CAP + pn] = (u16)e;
        int pe = atomicAdd(&g_cnt[NN + e], 1);
        if (pe < CAP) g_bkt_e[e * CAP + pe] = (u16)n;
    }
}

// ---- fp32 -> fp16 convert ----
__global__ void k_f2h(const float* __restrict__ src, __half* __restrict__ dst, int n4) {
    int i = blockIdx.x * blockDim.x + threadIdx.x;
    if (i < n4) {
        float4 v = ((const float4*)src)[i];
        __half2 h0 = __floats2half2_rn(v.x, v.y);
        __half2 h1 = __floats2half2_rn(v.z, v.w);
        uint2 o;
        o.x = *(u32*)&h0;
        o.y = *(u32*)&h1;
        ((uint2*)dst)[i] = o;
    }
}

// ---- tensor-core GEMM ----
__global__ __launch_bounds__(256) void k_gemm_mma(const __half* __restrict__ A,
                                                  const __half* __restrict__ Wh,
                                                  __half* __restrict__ C, int M) {
    extern __shared__ __half smem[];
    __half* sA = smem;
    __half* sB = smem + 128 * ASTRIDE;
    int tid = threadIdx.x;
    int rb = blockIdx.x * 128;

#pragma unroll
    for (int it = 0; it < 8; it++) {
        int idx = (it * 256 + tid) * 8;
        int r = idx >> 7, c = idx & 127;
        uint4 v = make_uint4(0, 0, 0, 0);
        if (rb + r < M) v = *(const uint4*)(A + (size_t)(rb + r) * HID + c);
        *(uint4*)(sA + r * ASTRIDE + c) = v;
    }
#pragma unroll
    for (int it = 0; it < 8; it++) {
        int idx = (it * 256 + tid) * 8;
        int r = idx >> 7, c = idx & 127;
        *(uint4*)(sB + r * ASTRIDE + c) = *(const uint4*)(Wh + r * HID + c);
    }
    __syncthreads();

    int w = tid >> 5, lane = tid & 31;
    int wm = (w & 3) * 32;
    int wn = (w >> 2) * 64;
    int lrow = (lane & 7) + ((lane >> 3) & 1) * 8;
    int lcol8 = (lane >> 4) * 8;

    float acc[2][8][4];
#pragma unroll
    for (int mi = 0; mi < 2; mi++)
#pragma unroll
        for (int nj = 0; nj < 8; nj++)
#pragma unroll
            for (int q = 0; q < 4; q++) acc[mi][nj][q] = 0.f;

#pragma unroll
    for (int ks = 0; ks < 8; ks++) {
        int k0 = ks * 16;
        u32 a[2][4];
#pragma unroll
        for (int mi = 0; mi < 2; mi++) {
            u32 ad = sptr(sA + (wm + mi * 16 + lrow) * ASTRIDE + k0 + lcol8);
            ldsm4(a[mi][0], a[mi][1], a[mi][2], a[mi][3], ad);
        }
        u32 b[8][2];
#pragma unroll
        for (int nj = 0; nj < 4; nj++) {
            u32 ad = sptr(sB + (k0 + lrow) * ASTRIDE + wn + nj * 16 + lcol8);
            u32 r0, r1, r2, r3;
            ldsm4t(r0, r1, r2, r3, ad);
            b[nj * 2][0] = r0; b[nj * 2][1] = r1;
            b[nj * 2 + 1][0] = r2; b[nj * 2 + 1][1] = r3;
        }
#pragma unroll
        for (int mi = 0; mi < 2; mi++)
#pragma unroll
            for (int nj = 0; nj < 8; nj++)
                mma16816(acc[mi][nj], a[mi], b[nj]);
    }

    int g = lane >> 2, t4 = lane & 3;
#pragma unroll
    for (int mi = 0; mi < 2; mi++) {
        int r0 = rb + wm + mi * 16 + g;
        int r1 = r0 + 8;
#pragma unroll
        for (int nj = 0; nj < 8; nj++) {
            int col = wn + nj * 8 + t4 * 2;
            if (r0 < M) {
                __half2 h = __floats2half2_rn(acc[mi][nj][0], acc[mi][nj][1]);
                *(__half2*)(C + (size_t)r0 * HID + col) = h;
            }
            if (r1 < M) {
                __half2 h = __floats2half2_rn(acc[mi][nj][2], acc[mi][nj][3]);
                *(__half2*)(C + (size_t)r1 * HID + col) = h;
            }
        }
    }
}

// ---- accumulate 8 halfs (uint4) into 8 floats ----
__device__ __forceinline__ void acc_row4(float* acc, uint4 u) {
    const __half2* hp = (const __half2*)&u;
#pragma unroll
    for (int q = 0; q < 4; q++) {
        float2 f = __half22float2(hp[q]);
        acc[2 * q]     += f.x;
        acc[2 * q + 1] += f.y;
    }
}

// ---- edge gather: m[e] = (1/B[e]) * sum xw[n], bucket CSR, inline inverse ----
__global__ __launch_bounds__(256) void k_gather_e(const __half* __restrict__ src,
                                                  __half* __restrict__ dst) {
    int g = blockIdx.x * blockDim.x + threadIdx.x;
    int e = g >> 5;
    int lane = g & 31;
    if (e >= NN) return;
    int c = g_cnt[NN + e];
    int len = c < CAP ? c : CAP;
    const u16* bkt = g_bkt_e + e * CAP;
    int half = lane >> 4, sub = lane & 15;
    float acc[8];
#pragma unroll
    for (int q = 0; q < 8; q++) acc[q] = 0.f;
    const uint4* s4 = (const uint4*)src;
    int j = 0;
    for (; j + 3 < len; j += 4) {
        int r0 = (int)bkt[j + half];
        int r1 = (int)bkt[j + 2 + half];
        uint4 u0 = s4[(size_t)r0 * 16 + sub];
        uint4 u1 = s4[(size_t)r1 * 16 + sub];
        acc_row4(acc, u0);
        acc_row4(acc, u1);
    }
    for (; j + 1 < len; j += 2) {
        int r0 = (int)bkt[j + half];
        uint4 u0 = s4[(size_t)r0 * 16 + sub];
        acc_row4(acc, u0);
    }
    if (j < len && half == 0) {
        int r0 = (int)bkt[j];
        uint4 u0 = s4[(size_t)r0 * 16 + sub];
        acc_row4(acc, u0);
    }
#pragma unroll
    for (int q = 0; q < 8; q++)
        acc[q] += __shfl_xor_sync(0xffffffffu, acc[q], 16);
    if (half == 0) {
        float s = c > 0 ? 1.0f / (float)c : 0.0f;
        __half2 h[4];
#pragma unroll
        for (int q = 0; q < 4; q++)
            h[q] = __floats2half2_rn(acc[2 * q] * s, acc[2 * q + 1] * s);
        ((uint4*)dst)[(size_t)e * 16 + sub] = *(uint4*)h;
    }
}

// ---- node gather: out[n] = prelu((1/D[n]) * sum m[e] + bias [+x]) ----
template <bool RES, typename OUT>
__global__ __launch_bounds__(256) void k_gather_n(const __half* __restrict__ src,
                                                  const float* __restrict__ bias,
                                                  const float* __restrict__ pa,
                                                  const float* __restrict__ xres,
                                                  OUT* __restrict__ dst) {
    int g = blockIdx.x * blockDim.x + threadIdx.x;
    int n = g >> 5;
    int lane = g & 31;
    if (n >= NN) return;
    int c = g_cnt[n];
    int len = c < CAP ? c : CAP;
    const u16* bkt = g_bkt_n + n * CAP;
    int half = lane >> 4, sub = lane & 15;
    float acc[8];
#pragma unroll
    for (int q = 0; q < 8; q++) acc[q] = 0.f;
    const uint4* s4 = (const uint4*)src;
    int j = 0;
    for (; j + 3 < len; j += 4) {
        int r0 = (int)bkt[j + half];
        int r1 = (int)bkt[j + 2 + half];
        uint4 u0 = s4[(size_t)r0 * 16 + sub];
        uint4 u1 = s4[(size_t)r1 * 16 + sub];
        acc_row4(acc, u0);
        acc_row4(acc, u1);
    }
    for (; j + 1 < len; j += 2) {
        int r0 = (int)bkt[j + half];
        uint4 u0 = s4[(size_t)r0 * 16 + sub];
        acc_row4(acc, u0);
    }
    if (j < len && half == 0) {
        int r0 = (int)bkt[j];
        uint4 u0 = s4[(size_t)r0 * 16 + sub];
        acc_row4(acc, u0);
    }
#pragma unroll
    for (int q = 0; q < 8; q++)
        acc[q] += __shfl_xor_sync(0xffffffffu, acc[q], 16);
    if (half == 0) {
        float d = c > 0 ? 1.0f / (float)c : 0.0f;
        float a = pa[0];
        float4 b0 = ((const float4*)bias)[sub * 2];
        float4 b1 = ((const float4*)bias)[sub * 2 + 1];
        float o[8];
        o[0] = acc[0] * d + b0.x; o[1] = acc[1] * d + b0.y;
        o[2] = acc[2] * d + b0.z; o[3] = acc[3] * d + b0.w;
        o[4] = acc[4] * d + b1.x; o[5] = acc[5] * d + b1.y;
        o[6] = acc[6] * d + b1.z; o[7] = acc[7] * d + b1.w;
        if (RES) {
            float4 x0 = ((const float4*)xres)[(size_t)n * 32 + sub * 2];
            float4 x1 = ((const float4*)xres)[(size_t)n * 32 + sub * 2 + 1];
            o[0] += x0.x; o[1] += x0.y; o[2] += x0.z; o[3] += x0.w;
            o[4] += x1.x; o[5] += x1.y; o[6] += x1.z; o[7] += x1.w;
        }
#pragma unroll
        for (int q = 0; q < 8; q++)
            o[q] = o[q] >= 0.f ? o[q] : a * o[q];
        if (sizeof(OUT) == 2) {
            __half2 h[4];
#pragma unroll
            for (int q = 0; q < 4; q++)
                h[q] = __floats2half2_rn(o[2 * q], o[2 * q + 1]);
            ((uint4*)dst)[(size_t)n * 16 + sub] = *(uint4*)h;
        } else {
            float4* dp = (float4*)dst;
            dp[(size_t)n * 32 + sub * 2]     = make_float4(o[0], o[1], o[2], o[3]);
            dp[(size_t)n * 32 + sub * 2 + 1] = make_float4(o[4], o[5], o[6], o[7]);
        }
    }
}

extern "C" void kernel_launch(void* const* d_in, const int* in_sizes, int n_in,
                              void* d_out, int out_size) {
    (void)in_sizes; (void)n_in; (void)out_size;
    const float* x   = (const float*)d_in[0];
    const void*  hei = d_in[1];
    const float* W1  = (const float*)d_in[2];
    const float* b1  = (const float*)d_in[3];
    const float* W2  = (const float*)d_in[4];
    const float* b2  = (const float*)d_in[5];
    const float* pa  = (const float*)d_in[6];
    float* out = (float*)d_out;

    __half *pxh, *pw1h, *pw2h, *pxw, *pm, *ph;
    cudaGetSymbolAddress((void**)&pxh,  g_xh);
    cudaGetSymbolAddress((void**)&pw1h, g_w1h);
    cudaGetSymbolAddress((void**)&pw2h, g_w2h);
    cudaGetSymbolAddress((void**)&pxw,  g_xw);
    cudaGetSymbolAddress((void**)&pm,   g_m);
    cudaGetSymbolAddress((void**)&ph,   g_h);

    const int GW_BLOCKS = (NN * 32) / 256;
    const int GEMM_SMEM = 2 * 128 * ASTRIDE * 2;
    cudaFuncSetAttribute(k_gemm_mma, cudaFuncAttributeMaxDynamicSharedMemorySize, GEMM_SMEM);

    // fork
    cudaEventRecord(g_ss.evStart, 0);
    cudaStreamWaitEvent(g_ss.s1, g_ss.evStart, 0);

    // stream 0: zero+detect -> bucket fill (both CSR sides, one pass)
    k_zero_detect<<<(2 * NN + 255) / 256, 256>>>((const long long*)hei);
    k_fill<<<(NE / 2 + 255) / 256, 256>>>(hei);
    cudaEventRecord(g_ss.evFill, 0);

    // s1: fp16 conversions + GEMM1 (joined before gather_e1)
    k_f2h<<<(NN * HID / 4 + 255) / 256, 256, 0, g_ss.s1>>>(x, pxh, NN * HID / 4);
    k_f2h<<<(HID * HID / 4 + 255) / 256, 256, 0, g_ss.s1>>>(W1, pw1h, HID * HID / 4);
    k_f2h<<<(HID * HID / 4 + 255) / 256, 256, 0, g_ss.s1>>>(W2, pw2h, HID * HID / 4);
    k_gemm_mma<<<(NN + 127) / 128, 256, GEMM_SMEM, g_ss.s1>>>(pxh, pw1h, pxw, NN);
    cudaEventRecord(g_ss.evGemm, g_ss.s1);

    // layer 1 aggregation
    cudaStreamWaitEvent(0, g_ss.evGemm, 0);
    k_gather_e<<<GW_BLOCKS, 256>>>(pxw, pm);
    k_gather_n<false, __half><<<GW_BLOCKS, 256>>>(pm, b1, pa, nullptr, ph);

    // layer 2
    k_gemm_mma<<<(NN + 127) / 128, 256, GEMM_SMEM>>>(ph, pw2h, pxw, NN);
    k_gather_e<<<GW_BLOCKS, 256>>>(pxw, pm);
    k_gather_n<true, float><<<GW_BLOCKS, 256>>>(pm, b2, pa, x, out);
}